// round 14
// baseline (speedup 1.0000x reference)
#include <cuda_runtime.h>
#include <cuda_fp16.h>
#include <cstdint>

#define D      128
#define NQ     512
#define NREF   100000
#define KNN    10
#define NSPLIT 36
#define NCH    22            // 36*22*128 = 101376 >= 100000
#define BN     128
#define NCAND  (NSPLIT * KNN)   // 360 candidates per query
#define ROWB   272           // smem tile row stride in bytes (136 fp16)
#define TILEB  (128 * ROWB)  // 34816 B per fp16 tile
#define SDS    132           // dist buffer row stride (floats)
#define SDBUF  (128 * SDS * 4)   // 67584 B per dist buffer
#define SY2_OFF (2 * TILEB + 2 * SDBUF)
// layout: B0 | B1 | sD0 | sD1 | y2[2][128]   (A tile overlays sD0 in prologue)
#define SMEM_BYTES (SY2_OFF + 2 * 128 * 4)   // 205824 B

#define BIGF 3.0e37f

// ---------------------------------------------------------------- scratch
__device__ float g_cand[NQ * NCAND];          // [q][360] for coalesced finalize

// ---------------------------------------------------------------- helpers
__device__ __forceinline__ uint32_t smem_u32(const void* p) {
    uint32_t a;
    asm("{ .reg .u64 t; cvta.to.shared.u64 t, %1; cvt.u32.u64 %0, t; }" : "=r"(a) : "l"(p));
    return a;
}

#define LDSM4(r, a)                                                            \
    asm volatile("ldmatrix.sync.aligned.m8n8.x4.shared.b16 {%0,%1,%2,%3}, [%4];" \
                 : "=r"((r)[0]), "=r"((r)[1]), "=r"((r)[2]), "=r"((r)[3])      \
                 : "r"(a))

// fp16-accumulate MMA
__device__ __forceinline__ void mma_f16(uint32_t* c, const uint32_t* a,
                                        uint32_t b0, uint32_t b1) {
    asm volatile("mma.sync.aligned.m16n8k16.row.col.f16.f16.f16.f16 "
                 "{%0,%1}, {%2,%3,%4,%5}, {%6,%7}, {%0,%1};"
                 : "+r"(c[0]), "+r"(c[1])
                 : "r"(a[0]), "r"(a[1]), "r"(a[2]), "r"(a[3]), "r"(b0), "r"(b1));
}

__device__ __forceinline__ void topk_insert(float (&tk)[KNN], float v) {
    if (v < tk[KNN - 1]) {
        tk[KNN - 1] = v;
        #pragma unroll
        for (int j = KNN - 1; j > 0; --j) {
            float lo = fminf(tk[j - 1], tk[j]);
            float hi = fmaxf(tk[j - 1], tk[j]);
            tk[j - 1] = lo;
            tk[j]     = hi;
        }
    }
}

// pack float4 -> 4 fp16 (uint2)
__device__ __forceinline__ uint2 pack_hf(float4 v) {
    __half2 h0 = __floats2half2_rn(v.x, v.y);
    __half2 h1 = __floats2half2_rn(v.z, v.w);
    uint2 p;
    p.x = *(uint32_t*)&h0;
    p.y = *(uint32_t*)&h1;
    return p;
}

// ---------------------------------------------------------------- kernel 1: fused mma main (512 thr)
__global__ void __launch_bounds__(512, 1)
knn_main_kernel(const float* __restrict__ feat, const float* __restrict__ refs) {
    extern __shared__ __align__(16) unsigned char smem[];
    const uint32_t sB0u = smem_u32(smem);
    const uint32_t sD0u = sB0u + 2 * TILEB;          // A staging in prologue
    float* sD0 = (float*)(smem + 2 * TILEB);
    float* sD1 = (float*)(smem + 2 * TILEB + SDBUF);
    float* sy2 = (float*)(smem + SY2_OFF);           // [2][128]

    const int t  = threadIdx.x;
    const int w  = t >> 5, l = t & 31;
    const int wm = w >> 1, wn = w & 1;     // warp grid 8(m) x 2(n), tile 16x64
    const int gr = l >> 2, lc = l & 3;     // C-fragment lane coords
    const int phase = l >> 3, pi = l & 7;  // ldmatrix lane roles

    const int split = blockIdx.x;
    const int qbase = blockIdx.y * 128;
    const int sbase = split * NCH * BN;

    // ldmatrix addresses
    const int prow = (phase & 1) * 8 + pi;
    const int pkof = (phase >> 1) * 16;
    const uint32_t aaddr = sD0u + (uint32_t)((wm * 16 + prow) * ROWB + pkof);
    uint32_t boff[4];
    {
        const int bn  = (phase >> 1) * 8 + pi;
        const int bkof = (phase & 1) * 16;
        #pragma unroll
        for (int g = 0; g < 4; ++g)
            boff[g] = (uint32_t)((wn * 64 + g * 16 + bn) * ROWB + bkof);
    }

    // ---- prologue: A (feat) fp32 -> fp16 into sD0 region
    {
        const float4* f4 = (const float4*)feat;      // row stride = 32 float4
        #pragma unroll
        for (int i = 0; i < 8; ++i) {
            const int row = w + 16 * i;              // warp owns whole rows
            float4 v = f4[(size_t)(qbase + row) * 32 + l];
            *(uint2*)(smem + 2 * TILEB + row * ROWB + l * 8) = pack_hf(v);
        }
    }
    __syncthreads();

    // hoist ALL A fragments; fill B0 + y2[0] inline (independent of afr)
    uint32_t afr[8][4];
    #pragma unroll
    for (int ks = 0; ks < 8; ++ks) LDSM4(afr[ks], aaddr + ks * 32);
    {
        const float4* r4 = (const float4*)refs;
        #pragma unroll
        for (int i = 0; i < 8; ++i) {
            const int row = w + 16 * i;
            const int grow = sbase + row;
            const int gc = grow < NREF ? grow : NREF - 1;
            float4 v = r4[(size_t)gc * 32 + l];
            float p = v.x * v.x + v.y * v.y + v.z * v.z + v.w * v.w;
            #pragma unroll
            for (int o = 16; o; o >>= 1) p += __shfl_xor_sync(0xffffffffu, p, o);
            if (l == 0) sy2[row] = (grow < NREF) ? p : BIGF;
            *(uint2*)(smem + row * ROWB + l * 8) = pack_hf(v);
        }
    }
    __syncthreads();   // afr reads done (sD0 free) + B0/sy2[0] visible

    float tk[KNN];
    #pragma unroll
    for (int j = 0; j < KNN; ++j) tk[j] = BIGF;

    float4 stage[8];

    for (int ch = 0; ch < NCH; ++ch) {
        const int cbase = sbase + ch * BN;
        const uint32_t Bcur = sB0u + (uint32_t)(ch & 1) * TILEB;
        float* sDw = (ch & 1) ? sD1 : sD0;
        float* sDr = (ch & 1) ? sD0 : sD1;
        const float* sy2c = sy2 + (ch & 1) * 128;
        const bool pf = (ch + 1 < NCH);

        // issue next chunk's fp32 loads (latency hidden under k-loop)
        if (pf) {
            const float4* r4 = (const float4*)refs;
            const int nbase = cbase + BN;
            #pragma unroll
            for (int i = 0; i < 8; ++i) {
                const int grow = nbase + w + 16 * i;
                const int gc = grow < NREF ? grow : NREF - 1;
                stage[i] = r4[(size_t)gc * 32 + l];
            }
        }

        uint32_t acc[8][2];
        #pragma unroll
        for (int j = 0; j < 8; ++j) { acc[j][0] = 0u; acc[j][1] = 0u; }

        #pragma unroll
        for (int ks = 0; ks < 8; ++ks) {
            const uint32_t kb = ks * 32;
            #pragma unroll
            for (int g = 0; g < 4; ++g) {
                uint32_t bf[4];
                LDSM4(bf, Bcur + boff[g] + kb);
                mma_f16(acc[2 * g],     afr[ks], bf[0], bf[1]);
                mma_f16(acc[2 * g + 1], afr[ks], bf[2], bf[3]);
            }
        }

        // selection of PREVIOUS chunk (acc-independent -> fills tensor bubbles)
        if (ch > 0) {
            const int q = t & 127, s = t >> 7;
            const float4* rowp = (const float4*)(sDr + q * SDS + s * 32);
            #pragma unroll
            for (int c = 0; c < 8; ++c) {
                const float4 v = rowp[c];
                const float m = fminf(fminf(v.x, v.y), fminf(v.z, v.w));
                if (m < tk[KNN - 1]) {
                    topk_insert(tk, v.x);
                    topk_insert(tk, v.y);
                    topk_insert(tk, v.z);
                    topk_insert(tk, v.w);
                }
            }
        }

        // convert stage -> B(ch+1) + y2[(ch+1)&1]  (nobody reads that buffer this iter)
        if (pf) {
            const int nb = (ch + 1) & 1;
            unsigned char* Bn = smem + (size_t)nb * TILEB;
            float* sy2n = sy2 + nb * 128;
            const int nbase = cbase + BN;
            #pragma unroll
            for (int i = 0; i < 8; ++i) {
                const int row = w + 16 * i;
                const float4 v = stage[i];
                float p = v.x * v.x + v.y * v.y + v.z * v.z + v.w * v.w;
                #pragma unroll
                for (int o = 16; o; o >>= 1) p += __shfl_xor_sync(0xffffffffu, p, o);
                if (l == 0) sy2n[row] = (nbase + row < NREF) ? p : BIGF;
                *(uint2*)(Bn + row * ROWB + l * 8) = pack_hf(v);
            }
        }

        // epilogue: d^2' = y^2 - 2*dot -> sDw
        {
            const int r0 = wm * 16 + gr;
            #pragma unroll
            for (int j = 0; j < 8; ++j) {
                const int c0 = wn * 64 + j * 8 + 2 * lc;
                const float2 yy = *(const float2*)(sy2c + c0);
                const float2 dlo = __half22float2(*(__half2*)&acc[j][0]);
                const float2 dhi = __half22float2(*(__half2*)&acc[j][1]);
                float2 lo, hi;
                lo.x = fmaf(-2.f, dlo.x, yy.x);
                lo.y = fmaf(-2.f, dlo.y, yy.y);
                hi.x = fmaf(-2.f, dhi.x, yy.x);
                hi.y = fmaf(-2.f, dhi.y, yy.y);
                *(float2*)(sDw + r0 * SDS + c0)       = lo;
                *(float2*)(sDw + (r0 + 8) * SDS + c0) = hi;
            }
        }
        __syncthreads();
    }

    // tail: select last chunk
    {
        const int q = t & 127, s = t >> 7;
        float* sDr = ((NCH - 1) & 1) ? sD1 : sD0;
        const float4* rowp = (const float4*)(sDr + q * SDS + s * 32);
        #pragma unroll
        for (int c = 0; c < 8; ++c) {
            const float4 v = rowp[c];
            const float m = fminf(fminf(v.x, v.y), fminf(v.z, v.w));
            if (m < tk[KNN - 1]) {
                topk_insert(tk, v.x);
                topk_insert(tk, v.y);
                topk_insert(tk, v.z);
                topk_insert(tk, v.w);
            }
        }
    }

    // merge 4 selectors' sorted lists per query (staged into sD0 region)
    __syncthreads();
    {
        const int q = t & 127, s = t >> 7;
        #pragma unroll
        for (int j = 0; j < KNN; ++j) sD0[(s * 11 + j) * 128 + q] = tk[j];
        sD0[(s * 11 + KNN) * 128 + q] = BIGF;   // sentinel
    }
    __syncthreads();
    if (t < 128) {
        int i0 = 0, i1 = 0, i2 = 0, i3 = 0;
        float* dst = g_cand + (size_t)(qbase + t) * NCAND + split * KNN;
        #pragma unroll
        for (int o = 0; o < KNN; ++o) {
            const float h0 = sD0[(i0)      * 128 + t];
            const float h1 = sD0[(11 + i1) * 128 + t];
            const float h2 = sD0[(22 + i2) * 128 + t];
            const float h3 = sD0[(33 + i3) * 128 + t];
            const float m = fminf(fminf(h0, h1), fminf(h2, h3));
            dst[o] = m;
            if (m == h0)      ++i0;
            else if (m == h1) ++i1;
            else if (m == h2) ++i2;
            else              ++i3;
        }
    }
}

// ---------------------------------------------------------------- kernel 2: finalize (warp/query, inline x2)
__global__ void __launch_bounds__(256)
finalize_kernel(const float* __restrict__ feat, float* __restrict__ out) {
    const int w = threadIdx.x >> 5, l = threadIdx.x & 31;
    const int q = blockIdx.x * 8 + w;
    if (q >= NQ) return;
    const float* cp = g_cand + (size_t)q * NCAND;

    // x2 inline: one float4 per lane + butterfly reduce
    float x2;
    {
        const float4 v = ((const float4*)(feat + (size_t)q * D))[l];
        float p = v.x * v.x + v.y * v.y + v.z * v.z + v.w * v.w;
        #pragma unroll
        for (int o = 16; o; o >>= 1) p += __shfl_xor_sync(0xffffffffu, p, o);
        x2 = p;
    }

    float tk[KNN];
    #pragma unroll
    for (int j = 0; j < KNN; ++j) tk[j] = BIGF;
    #pragma unroll
    for (int j = 0; j < 12; ++j) {
        const int i = l + j * 32;
        if (i < NCAND) {
            const float d2 = fmaxf(x2 + cp[i], 0.f);   // clamp -> bits monotone
            topk_insert(tk, d2);
        }
    }
    // 10-round warp merge via uint min-reduce
    float sum = 0.f;
    #pragma unroll
    for (int o = 0; o < KNN; ++o) {
        const unsigned hb = __float_as_uint(tk[0]);
        const unsigned mb = __reduce_min_sync(0xffffffffu, hb);
        sum += sqrtf(__uint_as_float(mb));
        const unsigned msk = __ballot_sync(0xffffffffu, hb == mb);
        if (l == __ffs(msk) - 1) {
            #pragma unroll
            for (int j = 0; j < KNN - 1; ++j) tk[j] = tk[j + 1];
            tk[KNN - 1] = BIGF;
        }
    }
    if (l == 0) out[q] = -sum * (1.0f / KNN);
}

// ---------------------------------------------------------------- launch
extern "C" void kernel_launch(void* const* d_in, const int* in_sizes, int n_in,
                              void* d_out, int out_size) {
    const float* feat = (const float*)d_in[0];
    const float* refs = (const float*)d_in[1];
    if (n_in >= 2 && in_sizes[0] > in_sizes[1]) {
        feat = (const float*)d_in[1];
        refs = (const float*)d_in[0];
    }

    cudaFuncSetAttribute(knn_main_kernel,
                         cudaFuncAttributeMaxDynamicSharedMemorySize, SMEM_BYTES);

    dim3 grid(NSPLIT, NQ / 128);
    knn_main_kernel<<<grid, 512, SMEM_BYTES>>>(feat, refs);

    finalize_kernel<<<NQ / 8, 256>>>(feat, (float*)d_out);
}

// round 15
// speedup vs baseline: 1.0916x; 1.0916x over previous
#include <cuda_runtime.h>
#include <cuda_fp16.h>
#include <cstdint>

#define D      128
#define NQ     512
#define NREF   100000
#define KNN    10
#define NSPLIT 36
#define NCH    22            // 36*22*128 = 101376 >= 100000
#define BN     128
#define NCAND  (NSPLIT * KNN)   // 360 candidates per query
#define ROWB   272           // smem tile row stride in bytes (136 fp16)
#define TILEB  (128 * ROWB)  // 34816 B per fp16 tile
#define SDS    132           // dist buffer row stride (floats)
#define SDBUF  (128 * SDS * 4)   // 67584 B per dist buffer
// layout: B0 | B1 | sD0 | sD1   (A tile overlays sD0 during prologue only)
#define SMEM_BYTES (2 * TILEB + 2 * SDBUF)   // 204800 B

#define BIGF 3.0e37f

// ---------------------------------------------------------------- scratch
__device__ float g_x2[NQ];
__device__ float g_y2[NREF];
__device__ float g_cand[NQ * NCAND];          // [q][360] for coalesced finalize
__device__ __half g_feat_hf[NQ * D];
__device__ __half g_refs_hf[NREF * D];

// ---------------------------------------------------------------- helpers
__device__ __forceinline__ uint32_t smem_u32(const void* p) {
    uint32_t a;
    asm("{ .reg .u64 t; cvta.to.shared.u64 t, %1; cvt.u32.u64 %0, t; }" : "=r"(a) : "l"(p));
    return a;
}
__device__ __forceinline__ void cpa16(uint32_t dst, const void* src, int bytes) {
    asm volatile("cp.async.cg.shared.global [%0], [%1], 16, %2;"
                 :: "r"(dst), "l"(src), "r"(bytes) : "memory");
}
#define CPA_COMMIT() asm volatile("cp.async.commit_group;" ::: "memory")
#define CPA_WAIT0()  asm volatile("cp.async.wait_group 0;" ::: "memory")
#define CPA_WAIT1()  asm volatile("cp.async.wait_group 1;" ::: "memory")

#define LDSM4(r, a)                                                            \
    asm volatile("ldmatrix.sync.aligned.m8n8.x4.shared.b16 {%0,%1,%2,%3}, [%4];" \
                 : "=r"((r)[0]), "=r"((r)[1]), "=r"((r)[2]), "=r"((r)[3])      \
                 : "r"(a))

// fp16-accumulate MMA: D,C are 2x b32 (4 halves)
__device__ __forceinline__ void mma_f16(uint32_t* c, const uint32_t* a,
                                        uint32_t b0, uint32_t b1) {
    asm volatile("mma.sync.aligned.m16n8k16.row.col.f16.f16.f16.f16 "
                 "{%0,%1}, {%2,%3,%4,%5}, {%6,%7}, {%0,%1};"
                 : "+r"(c[0]), "+r"(c[1])
                 : "r"(a[0]), "r"(a[1]), "r"(a[2]), "r"(a[3]), "r"(b0), "r"(b1));
}

__device__ __forceinline__ void topk_insert(float (&tk)[KNN], float v) {
    if (v < tk[KNN - 1]) {
        tk[KNN - 1] = v;
        #pragma unroll
        for (int j = KNN - 1; j > 0; --j) {
            float lo = fminf(tk[j - 1], tk[j]);
            float hi = fmaxf(tk[j - 1], tk[j]);
            tk[j - 1] = lo;
            tk[j]     = hi;
        }
    }
}

// Load 128x128 fp16 tile into smem [row][k], row stride ROWB bytes. 512 threads.
__device__ __forceinline__ void load_tile_hf(uint32_t dst, const __half* __restrict__ src,
                                             int gbase, int glimit) {
    const int t = threadIdx.x;
    const int c = t & 15;           // 16B chunk along k
    const int rb = t >> 4;          // row base (0..31)
    #pragma unroll
    for (int i = 0; i < 4; ++i) {
        const int row = rb + i * 32;
        const int gr = gbase + row;
        const int ok = (gr < glimit) ? 16 : 0;
        const int gc = (gr < glimit) ? gr : (glimit - 1);
        const __half* s = src + (size_t)gc * D + c * 8;
        cpa16(dst + (uint32_t)(row * ROWB + c * 16), s, ok);
    }
}

// ---------------------------------------------------------------- kernel 1: norms + fp16 convert
// 8 rows per warp (MLP=8) for deeper memory-level parallelism.
__global__ void __launch_bounds__(256)
norms_kernel(const float* __restrict__ feat, const float* __restrict__ refs) {
    const int w = threadIdx.x >> 5, l = threadIdx.x & 31;
    const int base_row = (blockIdx.x * 8 + w) * 8;     // 8 rows per warp
    const float* srcp;
    float* dst;
    __half* hdst;
    if (base_row < NREF) {                             // NREF % 8 == 0: no straddle
        srcp = refs + (size_t)base_row * D; dst = g_y2 + base_row;
        hdst = g_refs_hf + (size_t)base_row * D;
    } else {
        int r = base_row - NREF;
        if (r >= NQ) return;
        srcp = feat + (size_t)r * D; dst = g_x2 + r;
        hdst = g_feat_hf + (size_t)r * D;
    }
    const float4* s4 = (const float4*)srcp;
    float4 v[8];
    #pragma unroll
    for (int i = 0; i < 8; ++i) v[i] = s4[l + 32 * i];   // 8 outstanding LDG.128
    float s[8];
    #pragma unroll
    for (int i = 0; i < 8; ++i) {
        s[i] = v[i].x * v[i].x + v[i].y * v[i].y + v[i].z * v[i].z + v[i].w * v[i].w;
        __half2 p0 = __floats2half2_rn(v[i].x, v[i].y);
        __half2 p1 = __floats2half2_rn(v[i].z, v[i].w);
        uint2 packed;
        packed.x = *(uint32_t*)&p0;
        packed.y = *(uint32_t*)&p1;
        ((uint2*)(hdst + (size_t)i * D))[l] = packed;
    }
    #pragma unroll
    for (int o = 16; o; o >>= 1) {
        #pragma unroll
        for (int i = 0; i < 8; ++i) s[i] += __shfl_xor_sync(0xffffffffu, s[i], o);
    }
    if (l == 0) {
        *(float4*)dst       = make_float4(s[0], s[1], s[2], s[3]);
        *(float4*)(dst + 4) = make_float4(s[4], s[5], s[6], s[7]);
    }
}

// ---------------------------------------------------------------- kernel 2: fp16 mma main (512 thr)
__global__ void __launch_bounds__(512, 1)
knn_main_kernel() {
    extern __shared__ __align__(16) unsigned char smem[];
    const uint32_t sB0u = smem_u32(smem);
    const uint32_t sB1u = sB0u + TILEB;
    const uint32_t sD0u = sB0u + 2 * TILEB;          // also A staging in prologue
    float* sD0 = (float*)(smem + 2 * TILEB);
    float* sD1 = (float*)(smem + 2 * TILEB + SDBUF);

    const int t  = threadIdx.x;
    const int w  = t >> 5, l = t & 31;
    const int wm = w >> 1, wn = w & 1;     // warp grid 8(m) x 2(n), tile 16x64
    const int gr = l >> 2, lc = l & 3;     // C-fragment lane coords
    const int phase = l >> 3, pi = l & 7;  // ldmatrix lane roles

    const int split = blockIdx.x;
    const int qbase = blockIdx.y * 128;
    const int sbase = split * NCH * BN;

    // ldmatrix addresses
    const int prow = (phase & 1) * 8 + pi;
    const int pkof = (phase >> 1) * 16;
    const uint32_t aaddr = sD0u + (uint32_t)((wm * 16 + prow) * ROWB + pkof);
    uint32_t boff[4];
    {
        const int bn  = (phase >> 1) * 8 + pi;
        const int bkof = (phase & 1) * 16;
        #pragma unroll
        for (int g = 0; g < 4; ++g)
            boff[g] = (uint32_t)((wn * 64 + g * 16 + bn) * ROWB + bkof);
    }

    // prologue: A -> sD0 region (one group), B0 (second group)
    load_tile_hf(sD0u, g_feat_hf, qbase, qbase + 128);
    CPA_COMMIT();
    load_tile_hf(sB0u, g_refs_hf, sbase, NREF);
    CPA_COMMIT();
    CPA_WAIT1();            // A resident (B0 may still be in flight)
    __syncthreads();

    // hoist ALL A fragments (K=128) into registers; A smem then dead
    uint32_t afr[8][4];
    #pragma unroll
    for (int ks = 0; ks < 8; ++ks) LDSM4(afr[ks], aaddr + ks * 32);
    __syncthreads();        // all A reads done before epilogue(ch0) overwrites sD0

    float tk[KNN];
    #pragma unroll
    for (int j = 0; j < KNN; ++j) tk[j] = BIGF;

    for (int ch = 0; ch < NCH; ++ch) {
        const int cbase = sbase + ch * BN;
        const uint32_t Bcur = (ch & 1) ? sB1u : sB0u;
        float* sDw = (ch & 1) ? sD1 : sD0;
        float* sDr = (ch & 1) ? sD0 : sD1;

        CPA_WAIT0();          // B(ch) resident
        __syncthreads();

        if (ch + 1 < NCH)
            load_tile_hf((ch & 1) ? sB0u : sB1u, g_refs_hf, cbase + BN, NREF);
        CPA_COMMIT();

        uint32_t acc[8][2];    // f16x2 accumulators: [0]=row gr, [1]=row gr+8
        #pragma unroll
        for (int j = 0; j < 8; ++j) { acc[j][0] = 0u; acc[j][1] = 0u; }

        #pragma unroll
        for (int ks = 0; ks < 8; ++ks) {
            const uint32_t kb = ks * 32;
            #pragma unroll
            for (int g = 0; g < 4; ++g) {
                uint32_t bf[4];
                LDSM4(bf, Bcur + boff[g] + kb);
                mma_f16(acc[2 * g],     afr[ks], bf[0], bf[1]);
                mma_f16(acc[2 * g + 1], afr[ks], bf[2], bf[3]);
            }
        }

        // selection of PREVIOUS chunk (independent of acc -> fills MMA bubbles)
        if (ch > 0) {
            const int q = t & 127, s = t >> 7;
            const float4* rowp = (const float4*)(sDr + q * SDS + s * 32);
            #pragma unroll
            for (int c = 0; c < 8; ++c) {
                const float4 v = rowp[c];
                const float m = fminf(fminf(v.x, v.y), fminf(v.z, v.w));
                if (m < tk[KNN - 1]) {
                    topk_insert(tk, v.x);
                    topk_insert(tk, v.y);
                    topk_insert(tk, v.z);
                    topk_insert(tk, v.w);
                }
            }
        }

        // epilogue: d^2' = y^2 - 2*dot -> sDw (float2 stores)
        {
            const int r0 = wm * 16 + gr;
            #pragma unroll
            for (int j = 0; j < 8; ++j) {
                const int c0 = wn * 64 + j * 8 + 2 * lc;
                const int n0 = cbase + c0;
                float ya, yb;
                if (n0 + 1 < NREF) {
                    const float2 yy = *(const float2*)(g_y2 + n0);
                    ya = yy.x; yb = yy.y;
                } else {
                    ya = (n0 < NREF) ? g_y2[n0] : BIGF;
                    yb = BIGF;
                }
                const float2 dlo = __half22float2(*(__half2*)&acc[j][0]);
                const float2 dhi = __half22float2(*(__half2*)&acc[j][1]);
                float2 lo, hi;
                lo.x = fmaf(-2.f, dlo.x, ya);
                lo.y = fmaf(-2.f, dlo.y, yb);
                hi.x = fmaf(-2.f, dhi.x, ya);
                hi.y = fmaf(-2.f, dhi.y, yb);
                *(float2*)(sDw + r0 * SDS + c0)       = lo;
                *(float2*)(sDw + (r0 + 8) * SDS + c0) = hi;
            }
        }
        __syncthreads();
    }

    // tail: select last chunk
    {
        const int q = t & 127, s = t >> 7;
        float* sDr = ((NCH - 1) & 1) ? sD1 : sD0;
        const float4* rowp = (const float4*)(sDr + q * SDS + s * 32);
        #pragma unroll
        for (int c = 0; c < 8; ++c) {
            const float4 v = rowp[c];
            const float m = fminf(fminf(v.x, v.y), fminf(v.z, v.w));
            if (m < tk[KNN - 1]) {
                topk_insert(tk, v.x);
                topk_insert(tk, v.y);
                topk_insert(tk, v.z);
                topk_insert(tk, v.w);
            }
        }
    }

    // merge 4 selectors' sorted lists per query (staged into sD0 region)
    __syncthreads();
    {
        const int q = t & 127, s = t >> 7;
        #pragma unroll
        for (int j = 0; j < KNN; ++j) sD0[(s * 11 + j) * 128 + q] = tk[j];
        sD0[(s * 11 + KNN) * 128 + q] = BIGF;   // sentinel
    }
    __syncthreads();
    if (t < 128) {
        int i0 = 0, i1 = 0, i2 = 0, i3 = 0;
        float* dst = g_cand + (size_t)(qbase + t) * NCAND + split * KNN;
        #pragma unroll
        for (int o = 0; o < KNN; ++o) {
            const float h0 = sD0[(i0)      * 128 + t];
            const float h1 = sD0[(11 + i1) * 128 + t];
            const float h2 = sD0[(22 + i2) * 128 + t];
            const float h3 = sD0[(33 + i3) * 128 + t];
            const float m = fminf(fminf(h0, h1), fminf(h2, h3));
            dst[o] = m;
            if (m == h0)      ++i0;
            else if (m == h1) ++i1;
            else if (m == h2) ++i2;
            else              ++i3;
        }
    }
}

// ---------------------------------------------------------------- kernel 3: finalize (warp/query)
__global__ void __launch_bounds__(256)
finalize_kernel(float* __restrict__ out) {
    const int w = threadIdx.x >> 5, l = threadIdx.x & 31;
    const int q = blockIdx.x * 8 + w;
    if (q >= NQ) return;
    const float* cp = g_cand + (size_t)q * NCAND;
    const float x2 = g_x2[q];

    float tk[KNN];
    #pragma unroll
    for (int j = 0; j < KNN; ++j) tk[j] = BIGF;
    #pragma unroll
    for (int j = 0; j < 12; ++j) {
        const int i = l + j * 32;
        if (i < NCAND) {
            const float d2 = fmaxf(x2 + cp[i], 0.f);   // clamp -> bits monotone
            topk_insert(tk, d2);
        }
    }
    // 10-round warp merge via uint min-reduce
    float sum = 0.f;
    #pragma unroll
    for (int o = 0; o < KNN; ++o) {
        const unsigned hb = __float_as_uint(tk[0]);
        const unsigned mb = __reduce_min_sync(0xffffffffu, hb);
        sum += sqrtf(__uint_as_float(mb));
        const unsigned msk = __ballot_sync(0xffffffffu, hb == mb);
        if (l == __ffs(msk) - 1) {
            #pragma unroll
            for (int j = 0; j < KNN - 1; ++j) tk[j] = tk[j + 1];
            tk[KNN - 1] = BIGF;
        }
    }
    if (l == 0) out[q] = -sum * (1.0f / KNN);
}

// ---------------------------------------------------------------- launch
extern "C" void kernel_launch(void* const* d_in, const int* in_sizes, int n_in,
                              void* d_out, int out_size) {
    const float* feat = (const float*)d_in[0];
    const float* refs = (const float*)d_in[1];
    if (n_in >= 2 && in_sizes[0] > in_sizes[1]) {
        feat = (const float*)d_in[1];
        refs = (const float*)d_in[0];
    }

    cudaFuncSetAttribute(knn_main_kernel,
                         cudaFuncAttributeMaxDynamicSharedMemorySize, SMEM_BYTES);

    // 8 rows/warp, 8 warps/block -> 64 rows per block
    norms_kernel<<<(NREF + NQ + 63) / 64, 256>>>(feat, refs);

    dim3 grid(NSPLIT, NQ / 128);
    knn_main_kernel<<<grid, 512, SMEM_BYTES>>>();

    finalize_kernel<<<NQ / 8, 256>>>((float*)d_out);
}